// round 7
// baseline (speedup 1.0000x reference)
#include <cuda_runtime.h>
#include <cuda_bf16.h>
#include <cstdint>

#define BB 16
#define PP 96
#define TT 128
#define VV 64
#define NN 16
#define DD 128

// ---------------------------------------------------------------------------
// PTX helpers
// ---------------------------------------------------------------------------
__device__ __forceinline__ uint32_t smem_to_u32(const void* p) {
    uint32_t a;
    asm("{ .reg .u64 t; cvta.to.shared.u64 t, %1; cvt.u32.u64 %0, t; }"
        : "=r"(a) : "l"(p));
    return a;
}
__device__ __forceinline__ void ldsm4(uint32_t* r, uint32_t addr) {
    asm volatile("ldmatrix.sync.aligned.m8n8.x4.shared.b16 {%0,%1,%2,%3}, [%4];"
        : "=r"(r[0]), "=r"(r[1]), "=r"(r[2]), "=r"(r[3]) : "r"(addr));
}
__device__ __forceinline__ void mma_bf16(float* d, const uint32_t* a,
                                         const uint32_t* b) {
    asm volatile(
        "mma.sync.aligned.m16n8k16.row.col.f32.bf16.bf16.f32 "
        "{%0,%1,%2,%3}, {%4,%5,%6,%7}, {%8,%9}, {%0,%1,%2,%3};"
        : "+f"(d[0]), "+f"(d[1]), "+f"(d[2]), "+f"(d[3])
        : "r"(a[0]), "r"(a[1]), "r"(a[2]), "r"(a[3]), "r"(b[0]), "r"(b[1]));
}
#define CVT_BF2(w, xhi, xlo) \
    asm("cvt.rn.bf16x2.f32 %0, %1, %2;" : "=r"(w) : "f"(xhi), "f"(xlo))
#define CP_ASYNC16(dst, src) \
    asm volatile("cp.async.ca.shared.global [%0], [%1], 16;" :: "r"(dst), "l"(src))
#define CP_COMMIT() asm volatile("cp.async.commit_group;" ::: "memory")
#define CP_WAIT0()  asm volatile("cp.async.wait_group 0;" ::: "memory")
#define CP_WAIT1()  asm volatile("cp.async.wait_group 1;" ::: "memory")

// split fp32 pair -> hi bf16x2 word + lo residual word (low half = x0)
__device__ __forceinline__ void split2(float x0, float x1, uint32_t& h, uint32_t& l) {
    CVT_BF2(h, x1, x0);
    float f0 = __uint_as_float(h << 16);
    float f1 = __uint_as_float(h & 0xFFFF0000u);
    CVT_BF2(l, x1 - f1, x0 - f0);
}

// ---------------------------------------------------------------------------
// Scratch
// ---------------------------------------------------------------------------
__device__ uint32_t g_kbh[BB*TT*VV*64];        // projected keys hi bf16x2 (rows t<32 used)
__device__ uint32_t g_kbl[BB*TT*VV*64];        // projected keys lo
__device__ uint32_t g_abh[BB*PP*VV*64];        // attn output hi bf16x2
__device__ uint32_t g_abl[BB*PP*VV*64];        // attn output lo
__device__ uint32_t g_Wbh[2 * 128 * 64];       // [Wq, Wkv] hi bf16x2
__device__ uint32_t g_Wbl[2 * 128 * 64];       // lo residuals

// ---------------------------------------------------------------------------
// Weight split prep (Wq, Wkv) for attn_q's cp.async
// ---------------------------------------------------------------------------
__global__ void w2bf(const float* __restrict__ Wq, const float* __restrict__ Wkv) {
    int w = blockIdx.y;
    const float* S = (w == 0) ? Wq : Wkv;
    int e = blockIdx.x * 256 + threadIdx.x;  // 0..8191 pairs
    uint32_t h, l;
    split2(S[e * 2], S[e * 2 + 1], h, l);
    g_Wbh[w * 8192 + e] = h;
    g_Wbl[w * 8192 + e] = l;
}

// ===========================================================================
// gemm_k / gemm_out shared pieces (256 threads, 8 warps 2m x 4n, 32-row tiles)
// ===========================================================================
static constexpr int OFF_BHI  = 0;        // W hi: 128 x 272B = 34816
static constexpr int OFF_BLO  = 34816;
static constexpr int OFF_A    = 69632;    // 2 stages x (hi 8704 + lo 8704)
static constexpr int STAGE_B  = 17408;
static constexpr int GEMM_SMEM = OFF_A + 2 * STAGE_B;   // 104448

static constexpr int NCTA = 296;
static constexpr int NKT  = 1024;         // t<32 key tiles (16 b x 2048 rows / 32)
static constexpr int NOT_ = BB*TT*VV/32;  // 4096 out tiles

// Load + split one 128x128 fp32 weight into SMEM (hi/lo, 272B row stride)
__device__ __forceinline__ void load_W(char* smem, const float* __restrict__ W, int t) {
#pragma unroll
    for (int i = 0; i < 32; i++) {
        int e = t + 256 * i;
        int j = e >> 6, w = e & 63;
        float2 p = *(const float2*)(W + 2 * e);
        uint32_t h, l;
        split2(p.x, p.y, h, l);
        *(uint32_t*)(smem + OFF_BHI + j * 272 + w * 4) = h;
        *(uint32_t*)(smem + OFF_BLO + j * 272 + w * 4) = l;
    }
}

// MMA over one 32-row A stage (8 warps: 2m x 4n, warp tile 16x32)
__device__ __forceinline__ void mma_stage(uint32_t sbase, int st, int lane,
                                          int warp_m, int warp_n, float acc[4][4]) {
    uint32_t a0 = sbase + OFF_A + st * STAGE_B
                + (uint32_t)(warp_m * 16 + (lane & 15)) * 272 + ((lane >> 4) * 16);
    int bj = warp_n * 32 + (lane & 7) + ((lane >> 4) * 8);
    uint32_t b0 = sbase + OFF_BHI + (uint32_t)bj * 272 + (((lane >> 3) & 1) * 16);
#pragma unroll
    for (int ks = 0; ks < 8; ks++) {
        uint32_t ah[4], al[4], bh[2][4], bl[2][4];
        ldsm4(ah, a0 + ks * 32);
        ldsm4(al, a0 + 8704 + ks * 32);
        ldsm4(bh[0], b0 + ks * 32);
        ldsm4(bh[1], b0 + 16 * 272 + ks * 32);
        ldsm4(bl[0], b0 + (OFF_BLO - OFF_BHI) + ks * 32);
        ldsm4(bl[1], b0 + (OFF_BLO - OFF_BHI) + 16 * 272 + ks * 32);
#pragma unroll
        for (int ni = 0; ni < 2; ni++)
#pragma unroll
            for (int s2 = 0; s2 < 2; s2++) {
                float* d = acc[2 * ni + s2];
                mma_bf16(d, ah, &bh[ni][2 * s2]);
                mma_bf16(d, ah, &bl[ni][2 * s2]);
                mma_bf16(d, al, &bh[ni][2 * s2]);
            }
    }
}

// ---------------------------------------------------------------------------
// gemm_k: project keys rows t<32 only -> split bf16 g_kb (for out-proj concat)
// Persistent grid 256, register-prefetched A pipeline.
// ---------------------------------------------------------------------------
__global__ void __launch_bounds__(256, 2)
gemm_k(const float* __restrict__ keys, const float* __restrict__ Wkv,
       const float* __restrict__ bkv) {
    extern __shared__ char smem[];
    const uint32_t sbase = smem_to_u32(smem);
    int t = threadIdx.x, lane = t & 31, wid = t >> 5;
    int warp_m = wid >> 2, warp_n = wid & 3;

    load_W(smem, Wkv, t);

    int ocol0 = warp_n * 32 + 2 * (lane & 3);
    float2 bv[4];
#pragma unroll
    for (int nf = 0; nf < 4; nf++) bv[nf] = *(const float2*)(bkv + ocol0 + nf * 8);

    const float4* keys4 = (const float4*)keys;
    auto gmrow = [](int tile) {                     // global key row of tile start
        return (tile >> 6) * 8192 + (tile & 63) * 32;
    };

    int tile = blockIdx.x;
    float4 ap[4];
#pragma unroll
    for (int i = 0; i < 4; i++)
        ap[i] = keys4[(size_t)gmrow(tile) * 32 + t + 256 * i];

    int st = 0;
    for (; tile < NKT; tile += gridDim.x) {
#pragma unroll
        for (int i = 0; i < 4; i++) {
            int e = t + 256 * i;
            int r = e >> 5, w = e & 31;
            uint32_t h0, h1, l0, l1;
            split2(ap[i].x, ap[i].y, h0, l0);
            split2(ap[i].z, ap[i].w, h1, l1);
            char* p = smem + OFF_A + st * STAGE_B + r * 272 + w * 8;
            *(uint2*)p = make_uint2(h0, h1);
            *(uint2*)(p + 8704) = make_uint2(l0, l1);
        }
        __syncthreads();

        int nxt = tile + gridDim.x;
        if (nxt < NKT) {
#pragma unroll
            for (int i = 0; i < 4; i++)
                ap[i] = keys4[(size_t)gmrow(nxt) * 32 + t + 256 * i];
        }

        float acc[4][4];
#pragma unroll
        for (int a = 0; a < 4; a++)
#pragma unroll
            for (int c = 0; c < 4; c++) acc[a][c] = 0.f;
        mma_stage(sbase, st, lane, warp_m, warp_n, acc);

        int gm = gmrow(tile);
        int orow = warp_m * 16 + (lane >> 2);
#pragma unroll
        for (int nf = 0; nf < 4; nf++) {
            int col = ocol0 + nf * 8;
            int wi = col >> 1;
            float* d = acc[nf];
            uint32_t h, l;
            size_t r0 = (size_t)(gm + orow);
            split2(d[0] + bv[nf].x, d[1] + bv[nf].y, h, l);
            g_kbh[r0 * 64 + wi] = h; g_kbl[r0 * 64 + wi] = l;
            split2(d[2] + bv[nf].x, d[3] + bv[nf].y, h, l);
            g_kbh[(r0 + 8) * 64 + wi] = h; g_kbl[(r0 + 8) * 64 + wi] = l;
        }
        st ^= 1;
    }
}

// ---------------------------------------------------------------------------
// gemm_out: persistent, cp.async-streamed split-bf16 A (g_kb / g_ab)
// ---------------------------------------------------------------------------
__global__ void __launch_bounds__(256, 2)
gemm_out(const float* __restrict__ Wout, const float* __restrict__ bout,
         float* __restrict__ out) {
    extern __shared__ char smem[];
    const uint32_t sbase = smem_to_u32(smem);
    int t = threadIdx.x, lane = t & 31, wid = t >> 5;
    int warp_m = wid >> 2, warp_n = wid & 3;

    load_W(smem, Wout, t);

    int ocol0 = warp_n * 32 + 2 * (lane & 3);
    float2 bv[4];
#pragma unroll
    for (int nf = 0; nf < 4; nf++) bv[nf] = *(const float2*)(bout + ocol0 + nf * 8);

    auto issueA = [&](int tile, int stg) {
        if (tile < NOT_) {
            int m0 = tile * 32;
            int b = m0 >> 13, tt = (m0 >> 6) & 127, v0 = m0 & 63;
            const uint32_t *sh, *sl;
            if (tt < 32) {
                sh = g_kbh + (size_t)m0 * 64;
                sl = g_kbl + (size_t)m0 * 64;
            } else {
                size_t rb = ((size_t)(b * PP + (tt - 32)) * VV + v0) * 64;
                sh = g_abh + rb;
                sl = g_abl + rb;
            }
            uint32_t dbase = sbase + OFF_A + stg * STAGE_B;
#pragma unroll
            for (int k = 0; k < 2; k++) {
                int c = t + 256 * k;
                uint32_t d = dbase + (c >> 4) * 272 + (c & 15) * 16;
                CP_ASYNC16(d, sh + 4 * c);
                CP_ASYNC16(d + 8704, sl + 4 * c);
            }
        }
        CP_COMMIT();
    };

    issueA(blockIdx.x, 0);
    issueA(blockIdx.x + NCTA, 1);

    int st = 0;
    for (int tile = blockIdx.x; tile < NOT_; tile += NCTA) {
        CP_WAIT1();
        __syncthreads();

        float acc[4][4];
#pragma unroll
        for (int a = 0; a < 4; a++)
#pragma unroll
            for (int c = 0; c < 4; c++) acc[a][c] = 0.f;
        mma_stage(sbase, st, lane, warp_m, warp_n, acc);

        int m0 = tile * 32;
        int orow = warp_m * 16 + (lane >> 2);
#pragma unroll
        for (int nf = 0; nf < 4; nf++) {
            int col = ocol0 + nf * 8;
            float* d = acc[nf];
            size_t r0 = (size_t)(m0 + orow);
            *(float2*)(out + r0 * DD + col) = make_float2(d[0] + bv[nf].x, d[1] + bv[nf].y);
            *(float2*)(out + (r0 + 8) * DD + col) = make_float2(d[2] + bv[nf].x, d[3] + bv[nf].y);
        }

        __syncthreads();
        issueA(tile + 2 * NCTA, st);
        st ^= 1;
    }
}

// ===========================================================================
// attn_q: one block per (b,p), 512 threads. Projects q AND k(t=32+p) in-SMEM
// (weights cp.async'd pre-split from L2), then does gather-attention.
// q and k(t>=32) never touch global memory.
// ===========================================================================
static constexpr int AQ_W   = 0;         // W hi 34816 + lo 34816 = 69632
static constexpr int AQ_A   = 69632;     // A stage: hi 17408 + lo 17408 (64 rows)
static constexpr int AQ_QO  = 104448;    // q fp32 64 x 132
static constexpr int AQ_KS  = 138240;    // k fp32 64 x 132
static constexpr int AQ_SMEM = 172032;

// 16 warps: 4m x 4n, warp tile 16 x 32 over 64x128
__device__ __forceinline__ void mma_64(uint32_t sbase, int lane,
                                       int warp_m, int warp_n, float acc[4][4]) {
    uint32_t a0 = sbase + AQ_A
                + (uint32_t)(warp_m * 16 + (lane & 15)) * 272 + ((lane >> 4) * 16);
    int bj = warp_n * 32 + (lane & 7) + ((lane >> 4) * 8);
    uint32_t b0 = sbase + AQ_W + (uint32_t)bj * 272 + (((lane >> 3) & 1) * 16);
#pragma unroll
    for (int ks = 0; ks < 8; ks++) {
        uint32_t ah[4], al[4], bh[2][4], bl[2][4];
        ldsm4(ah, a0 + ks * 32);
        ldsm4(al, a0 + 17408 + ks * 32);
        ldsm4(bh[0], b0 + ks * 32);
        ldsm4(bh[1], b0 + 16 * 272 + ks * 32);
        ldsm4(bl[0], b0 + 34816 + ks * 32);
        ldsm4(bl[1], b0 + 34816 + 16 * 272 + ks * 32);
#pragma unroll
        for (int ni = 0; ni < 2; ni++)
#pragma unroll
            for (int s2 = 0; s2 < 2; s2++) {
                float* d = acc[2 * ni + s2];
                mma_bf16(d, ah, &bh[ni][2 * s2]);
                mma_bf16(d, ah, &bl[ni][2 * s2]);
                mma_bf16(d, al, &bh[ni][2 * s2]);
            }
    }
}

__global__ void __launch_bounds__(512, 1)
attn_q(const float* __restrict__ queries, const float* __restrict__ keys,
       const int* __restrict__ ccc,
       const float* __restrict__ bq, const float* __restrict__ bkv) {
    extern __shared__ char smem[];
    const uint32_t sbase = smem_to_u32(smem);
    int t = threadIdx.x, lane = t & 31, wid = t >> 5;
    int warp_m = wid >> 2, warp_n = wid & 3;
    int bp = blockIdx.x;
    int b = bp / PP, p = bp % PP;

    // cp.async a pre-split weight (hi 2048 + lo 2048 chunks of 16B)
    auto issueW = [&](int sel) {
        const uint32_t* wh = g_Wbh + sel * 8192;
        const uint32_t* wl = g_Wbl + sel * 8192;
#pragma unroll
        for (int k = 0; k < 4; k++) {
            int c = t + 512 * k;
            uint32_t d = sbase + AQ_W + (c >> 4) * 272 + (c & 15) * 16;
            CP_ASYNC16(d, wh + 4 * c);
            CP_ASYNC16(d + 34816, wl + 4 * c);
        }
        CP_COMMIT();
    };
    // convert 64x128 fp32 (in regs) -> split A stage
    auto convertA = [&](const float4* ap) {
#pragma unroll
        for (int i = 0; i < 4; i++) {
            int e = t + 512 * i;
            int r = e >> 5, c4 = e & 31;
            uint32_t h0, h1, l0, l1;
            split2(ap[i].x, ap[i].y, h0, l0);
            split2(ap[i].z, ap[i].w, h1, l1);
            char* dst = smem + AQ_A + r * 272 + c4 * 8;
            *(uint2*)dst = make_uint2(h0, h1);
            *(uint2*)(dst + 17408) = make_uint2(l0, l1);
        }
    };
    int ocol0 = warp_n * 32 + 2 * (lane & 3);
    int orow  = warp_m * 16 + (lane >> 2);
    // write projection result + bias into a 132-stride fp32 smem region
    auto writeO = [&](int off, float acc[4][4], const float* bias) {
#pragma unroll
        for (int nf = 0; nf < 4; nf++) {
            int col = ocol0 + nf * 8;
            float2 bv = *(const float2*)(bias + col);
            float* d = acc[nf];
            *(float2*)(smem + off + orow * 528 + col * 4) =
                make_float2(d[0] + bv.x, d[1] + bv.y);
            *(float2*)(smem + off + (orow + 8) * 528 + col * 4) =
                make_float2(d[2] + bv.x, d[3] + bv.y);
        }
    };

    issueW(0);                                           // Wq
    const float4* q4p = (const float4*)queries + (size_t)bp * 2048;
    const float4* k4p = (const float4*)keys + (size_t)(b * TT + 32 + p) * 2048;
    float4 ap[4], kp[4];
#pragma unroll
    for (int i = 0; i < 4; i++) ap[i] = q4p[t + 512 * i];
#pragma unroll
    for (int i = 0; i < 4; i++) kp[i] = k4p[t + 512 * i]; // prefetch keys early
    convertA(ap);
    CP_WAIT0();
    __syncthreads();

    // q projection
    float acc[4][4];
#pragma unroll
    for (int a = 0; a < 4; a++)
#pragma unroll
        for (int c = 0; c < 4; c++) acc[a][c] = 0.f;
    mma_64(sbase, lane, warp_m, warp_n, acc);
    __syncthreads();                                     // done reading Wq + A

    issueW(1);                                           // Wkv (overlaps below)
    writeO(AQ_QO, acc, bq);
    convertA(kp);
    CP_WAIT0();
    __syncthreads();

    // k projection
#pragma unroll
    for (int a = 0; a < 4; a++)
#pragma unroll
        for (int c = 0; c < 4; c++) acc[a][c] = 0.f;
    mma_64(sbase, lane, warp_m, warp_n, acc);
    writeO(AQ_KS, acc, bkv);
    __syncthreads();

    // -------- attention (8 threads/head) --------
    int v = t >> 3, to = t & 7;
    float4 q4[4];
#pragma unroll
    for (int j = 0; j < 4; j++)
        q4[j] = *(const float4*)(smem + AQ_QO + v * 528 + (to + 8 * j) * 16);

    const int* cv = ccc + b * (VV * NN) + v * NN;
    const float scale = 0.08838834764831845f;

    float S = 0.f;
    float4 o[4];
#pragma unroll
    for (int j = 0; j < 4; j++) o[j] = make_float4(0.f, 0.f, 0.f, 0.f);

#pragma unroll
    for (int n = 0; n < NN; n++) {
        int kidx = cv[n];
        const char* kr = smem + AQ_KS + kidx * 528;
        float4 kv[4];
        float dot = 0.f;
#pragma unroll
        for (int j = 0; j < 4; j++) {
            kv[j] = *(const float4*)(kr + (to + 8 * j) * 16);
            dot += q4[j].x * kv[j].x + q4[j].y * kv[j].y
                 + q4[j].z * kv[j].z + q4[j].w * kv[j].w;
        }
        dot += __shfl_xor_sync(0xffffffffu, dot, 1);
        dot += __shfl_xor_sync(0xffffffffu, dot, 2);
        dot += __shfl_xor_sync(0xffffffffu, dot, 4);
        float w = __expf(dot * scale);
        S += w;
#pragma unroll
        for (int j = 0; j < 4; j++) {
            o[j].x += w * kv[j].x;
            o[j].y += w * kv[j].y;
            o[j].z += w * kv[j].z;
            o[j].w += w * kv[j].w;
        }
    }

    float inv = 1.f / S;
    size_t row = (size_t)bp * VV + v;
    uint2* dh = (uint2*)(g_abh + row * 64);
    uint2* dl = (uint2*)(g_abl + row * 64);
#pragma unroll
    for (int j = 0; j < 4; j++) {
        uint32_t h0, h1, l0, l1;
        split2(o[j].x * inv, o[j].y * inv, h0, l0);
        split2(o[j].z * inv, o[j].w * inv, h1, l1);
        dh[to + 8 * j] = make_uint2(h0, h1);
        dl[to + 8 * j] = make_uint2(l0, l1);
    }
}

// ---------------------------------------------------------------------------
extern "C" void kernel_launch(void* const* d_in, const int* in_sizes, int n_in,
                              void* d_out, int out_size) {
    const float* queries = (const float*)d_in[0];
    const float* keys    = (const float*)d_in[1];
    const int*   ccc     = (const int*)  d_in[2];
    const float* Wq      = (const float*)d_in[3];
    const float* bq      = (const float*)d_in[4];
    const float* Wkv     = (const float*)d_in[5];
    const float* bkv     = (const float*)d_in[6];
    const float* Wout    = (const float*)d_in[7];
    const float* bout    = (const float*)d_in[8];
    float* out = (float*)d_out;

    static bool attr_done = false;
    if (!attr_done) {
        cudaFuncSetAttribute(gemm_k,   cudaFuncAttributeMaxDynamicSharedMemorySize, GEMM_SMEM);
        cudaFuncSetAttribute(gemm_out, cudaFuncAttributeMaxDynamicSharedMemorySize, GEMM_SMEM);
        cudaFuncSetAttribute(attn_q,   cudaFuncAttributeMaxDynamicSharedMemorySize, AQ_SMEM);
        attr_done = true;
    }

    gemm_k<<<256, 256, GEMM_SMEM>>>(keys, Wkv, bkv);
    w2bf<<<dim3(32, 2), 256>>>(Wq, Wkv);
    attn_q<<<BB * PP, 512, AQ_SMEM>>>(queries, keys, ccc, bq, bkv);
    gemm_out<<<NCTA, 256, GEMM_SMEM>>>(Wout, bout, out);
}